// round 16
// baseline (speedup 1.0000x reference)
#include <cuda_runtime.h>
#include <math.h>

#define NSTEPS   10240
#define NBINS    257
#define BLK      512
#define HOP      256
#define PIANO    2621440
#define ENVLEN   327744
#define SQRTN_INV 0.04419417382415922f   // 1/sqrt(512)
#define TWO_PI   6.283185307179586f

// WARM=5: empirical per-step contraction ~0.15 -> truncation ~2e-6.
// CH=16: scan redundancy (WARM+CH-1)/CH = 1.25 (vs 1.5 at CH=8).
#define CH   16
#define WARM 5
#define NB_BC (NSTEPS / CH)   // 640 fused scan+iFFT blocks
#define SROW 264              // spec row stride (float2); 8 rows = 2112 = 4*528 FFT work

// padded row stride (float2) for the 8x64 transpose buffer
#define RPAD 66

// +1 row padding: final iteration's (unused) ispec prefetch may touch row NSTEPS.
__device__ float2 g_ispec[(NSTEPS + 1) * NBINS];

__device__ __forceinline__ float2 cmulf(float2 a, float2 b) {
    return make_float2(a.x * b.x - a.y * b.y, a.x * b.y + a.y * b.x);
}
__device__ __forceinline__ float2 cadd(float2 a, float2 b) { return make_float2(a.x + b.x, a.y + b.y); }
__device__ __forceinline__ float2 csub(float2 a, float2 b) { return make_float2(a.x - b.x, a.y - b.y); }
__device__ __forceinline__ float2 cmuli(float2 a, float dir) { return make_float2(-dir * a.y, dir * a.x); }

__device__ __forceinline__ void dft8(float2 a[8], float dir) {
    const float r = 0.70710678118654752f;
    float2 e0 = cadd(a[0], a[4]), e1 = csub(a[0], a[4]);
    float2 o0 = cadd(a[2], a[6]), o1 = cmuli(csub(a[2], a[6]), dir);
    float2 E0 = cadd(e0, o0), E1 = cadd(e1, o1), E2 = csub(e0, o0), E3 = csub(e1, o1);
    float2 f0 = cadd(a[1], a[5]), f1 = csub(a[1], a[5]);
    float2 g0 = cadd(a[3], a[7]), g1 = cmuli(csub(a[3], a[7]), dir);
    float2 O0 = cadd(f0, g0), O1 = cadd(f1, g1), O2 = csub(f0, g0), O3 = csub(f1, g1);
    O1 = cmulf(O1, make_float2( r, dir * r));
    O2 = cmuli(O2, dir);
    O3 = cmulf(O3, make_float2(-r, dir * r));
    a[0] = cadd(E0, O0); a[1] = cadd(E1, O1); a[2] = cadd(E2, O2); a[3] = cadd(E3, O3);
    a[4] = csub(E0, O0); a[5] = csub(E1, O1); a[6] = csub(E2, O2); a[7] = csub(E3, O3);
}

__device__ __forceinline__ void twiddle8(float2 a[8], float ang) {
    float s1, c1, s4, c4;
    __sincosf(ang, &s1, &c1);
    __sincosf(4.0f * ang, &s4, &c4);
    float2 w1 = make_float2(c1, s1), w4 = make_float2(c4, s4);
    float2 w2 = cmulf(w1, w1), w3 = cmulf(w2, w1);
    a[1] = cmulf(a[1], w1);
    a[2] = cmulf(a[2], w2);
    a[3] = cmulf(a[3], w3);
    a[4] = cmulf(a[4], w4);
    a[5] = cmulf(a[5], cmulf(w4, w1));
    a[6] = cmulf(a[6], cmulf(w4, w2));
    a[7] = cmulf(a[7], cmulf(w4, w3));
}

// 3-stage radix-8 512-pt FFT. Input: a[n1] = x[64*n1 + t], t in [0,64).
// Output: a[j2] = X[tp + 64*j2], tp = (t&7) + 8*(t>>3).
__device__ __forceinline__ void fft512_r8(float2 a[8], float2* W, int t, float dir) {
    dft8(a, dir);
    twiddle8(a, dir * TWO_PI * (float)t * (1.0f / 512.0f));
#pragma unroll
    for (int k1 = 0; k1 < 8; k1++) W[k1 * RPAD + t] = a[k1];
    __syncthreads();
    int k1 = t >> 3, m2 = t & 7;
#pragma unroll
    for (int m1 = 0; m1 < 8; m1++) a[m1] = W[k1 * RPAD + 8 * m1 + m2];
    dft8(a, dir);
    twiddle8(a, dir * TWO_PI * (float)m2 * (1.0f / 64.0f));
#pragma unroll
    for (int j1 = 0; j1 < 8; j1++) W[k1 * RPAD + 8 * j1 + m2] = a[j1];  // per-thread in-place
    __syncthreads();
    int j1 = t >> 3, k1b = t & 7;
#pragma unroll
    for (int q = 0; q < 8; q++) a[q] = W[k1b * RPAD + 8 * j1 + q];
    dft8(a, dir);
}

// Kernel A: forward excitation spectra + zero-init of OA boundary spans
// (even kA blocks map 1:1 to the 640 kBC tile-front spans).
__global__ void kA7(const float* __restrict__ env, const float* __restrict__ noise,
                    const float* __restrict__ etf_r, const float* __restrict__ etf_i,
                    float* __restrict__ out) {
    __shared__ float2 work[4][8 * RPAD];
    __shared__ float  exc [2304];
    __shared__ float  es  [290];
    int tid = threadIdx.x;
    int g = tid >> 6, t = tid & 63;
    const int base = blockIdx.x * 8;
    const int k0 = base + 2 * g;
    float2* W = work[g];

    if ((blockIdx.x & 1) == 0)
        out[(blockIdx.x >> 1) * 4096 + tid] = 0.0f;   // tile-front span zero-init

    {
        int g0i = base * 32 - 1;
        int i0 = g0i + tid;
        float e0 = __ldg(&env[max(i0, 0)]);
        es[tid] = e0 * e0;
        if (tid < 34) {
            float e1 = __ldg(&env[min(g0i + 256 + tid, ENVLEN - 1)]);
            es[256 + tid] = e1 * e1;
        }
    }
    __syncthreads();

#pragma unroll
    for (int u = 0; u < 9; u++) {
        int o = tid + 256 * u;
        int m = o >> 3, j = o & 7;
        int s_lo = m + (j >> 2);
        float w = 0.0625f + 0.125f * (float)((j + 4) & 7);
        float lo = es[s_lo], hi = es[s_lo + 1];
        exc[o] = lo + (hi - lo) * w;
    }
    __syncthreads();

    float2 a[8];
#pragma unroll
    for (int n1 = 0; n1 < 8; n1++) {
        int n = 64 * n1 + t;
        float v0 = noise[k0 * BLK + n]       * exc[2 * g * HOP + n];
        float v1 = noise[(k0 + 1) * BLK + n] * exc[(2 * g + 1) * HOP + n];
        a[n1] = make_float2(v0, v1);
    }
    fft512_r8(a, W, t, -1.0f);
    __syncthreads();

    int tp = (t & 7) + 8 * (t >> 3);
#pragma unroll
    for (int j2 = 0; j2 < 8; j2++) W[tp + 64 * j2] = a[j2];
    __syncthreads();

    for (int j = t; j < NBINS; j += 64) {
        float2 Z  = W[j];
        float2 Zc = W[(512 - j) & 511];
        Zc.y = -Zc.y;
        float2 X0 = make_float2(0.5f * (Z.x + Zc.x), 0.5f * (Z.y + Zc.y));
        float2 D  = make_float2(Z.x - Zc.x, Z.y - Zc.y);
        float2 X1 = make_float2(0.5f * D.y, -0.5f * D.x);
        X0.x *= SQRTN_INV; X0.y *= SQRTN_INV;
        X1.x *= SQRTN_INV; X1.y *= SQRTN_INV;
        float2 e = make_float2(etf_r[j], etf_i[j]);
        float2 I0 = cmulf(X0, e);
        float2 I1 = cmulf(X1, e);
        if (j == 0 || j == 256) { I0.y = 0.0f; I1.y = 0.0f; }
        g_ispec[k0 * NBINS + j]       = I0;
        g_ispec[(k0 + 1) * NBINS + j] = I1;
    }
}

// ---------------------------------------------------------------------------
// Kernel BC: fused scan (16 spectra, 20 iters) + 2 rounds of 4 paired IFFTs
// + overlap-add. spec tile (16 x SROW float2) aliases each round's FFT work
// region (8 rows = exactly 4 x 528). sh_hi slot 3 carries the cross-round
// OA span (blk7-hi -> blk8 even span).
// ---------------------------------------------------------------------------
__global__ void __launch_bounds__(256, 6)
kBC(const float* __restrict__ tf_r, const float* __restrict__ tf_i,
    float* __restrict__ out) {
    __shared__ float2 specF[16 * SROW];        // 33,792 B (spec + FFT work alias)
    __shared__ float  uni[1036];               // shY (2*259 f2) / sh_hi [4][256]
    float2* shY   = (float2*)uni;
    float*  sh_hi = uni;

    const int tid = threadIdx.x;
    const bool dual = (tid == 255);
    const int b = blockIdx.x;
    const int k0 = b * CH;

    // ---- Phase 1: scan ----
    int k_start = k0 - WARM;
    if (k_start < 0) k_start = 0;
    const int k_last = k0 + CH - 2;

    float2 S = g_ispec[k_start * NBINS + tid];
    float2 tfv = make_float2(__ldg(&tf_r[k_start * NBINS + tid]),
                             __ldg(&tf_i[k_start * NBINS + tid]));
    float2 iv  = g_ispec[(k_start + 1) * NBINS + tid];
    float S2 = 0.f, tf2 = 0.f, iv2 = 0.f;
    if (dual) {
        S2  = g_ispec[k_start * NBINS + 256].x;
        tf2 = __ldg(&tf_r[k_start * NBINS + 256]);
        iv2 = g_ispec[(k_start + 1) * NBINS + 256].x;
    }
    if (k_start == k0) {
        specF[tid] = S;
        if (dual) specF[256] = make_float2(S2, 0.f);
    }

    int p = 0;
#pragma unroll 2
    for (int kk = k_start; kk <= k_last; kk++, p ^= 1) {
        float2* buf = shY + p * 259;
        float2 Y = cmulf(tfv, S);
        if (tid == 0) Y.y = 0.0f;
        buf[tid + 1] = Y;
        if (tid == 1) buf[0] = make_float2(Y.x, -Y.y);
        float Y2 = 0.f;
        if (dual) {
            Y2 = tf2 * S2;                      // bin 256: real scalar
            buf[257] = make_float2(Y2, 0.0f);
        }
        int kn = kk + 1;
        float2 tfn = make_float2(__ldg(&tf_r[kn * NBINS + tid]),
                                 __ldg(&tf_i[kn * NBINS + tid]));
        float2 ivn = g_ispec[(kk + 2) * NBINS + tid];   // padded: no clamp
        float tfn2 = 0.f, ivn2 = 0.f;
        if (dual) {
            tfn2 = __ldg(&tf_r[kn * NBINS + 256]);
            ivn2 = g_ispec[(kk + 2) * NBINS + 256].x;
        }
        __syncthreads();
        float2 Ym = buf[tid];
        float2 Yp = buf[tid + 2];
        S.x = 0.54f * Y.x - 0.23f * (Ym.x + Yp.x) + iv.x;   // Y0 = own reg
        S.y = 0.54f * Y.y - 0.23f * (Ym.y + Yp.y) + iv.y;
        bool st = (kk + 1 >= k0);
        if (st) specF[(kk + 1 - k0) * SROW + tid] = S;
        if (dual) {
            S2 = 0.54f * Y2 - 0.46f * Y.x + iv2;
            if (st) specF[(kk + 1 - k0) * SROW + 256] = make_float2(S2, 0.f);
        }
        tfv = tfn; iv = ivn; tf2 = tfn2; iv2 = ivn2;
    }
    __syncthreads();    // spec complete; shY dead

    // ---- Phases 2+3: two rounds of 4 paired inverse FFTs + OA ----
    const int g = tid >> 6, t = tid & 63;
    const int tp = (t & 7) + 8 * (t >> 3);
#pragma unroll
    for (int r = 0; r < 2; r++) {
        float2 a[8];
        const float2* s0 = specF + (8 * r + 2 * g) * SROW;
        const float2* s1 = s0 + SROW;
#pragma unroll
        for (int n1 = 0; n1 < 8; n1++) {
            int n = 64 * n1 + t;
            if (n <= 256) {
                float2 S0 = s0[n], S1 = s1[n];
                a[n1] = make_float2(S0.x - S1.y, S0.y + S1.x);
            } else {
                int j = 512 - n;
                float2 S0 = s0[j], S1 = s1[j];
                a[n1] = make_float2(S0.x + S1.y, S1.x - S0.y);
            }
        }
        __syncthreads();    // reads done -> FFT may overwrite this round's region
        fft512_r8(a, specF + r * 8 * SROW + g * 528, t, +1.0f);

#pragma unroll
        for (int q = 0; q < 8; q++) { a[q].x *= SQRTN_INV; a[q].y *= SQRTN_INV; }

        if (g < 3) {   // stage blk hi for next group's even span (this round)
#pragma unroll
            for (int j2 = 0; j2 < 4; j2++) sh_hi[g * 256 + tp + 64 * j2] = a[j2 + 4].y;
        }
        if (g == 3 && r == 0) {   // blk7 hi -> cross-round slot for round-1 g=0
#pragma unroll
            for (int j2 = 0; j2 < 4; j2++) sh_hi[3 * 256 + tp + 64 * j2] = a[j2 + 4].y;
        }
#pragma unroll
        for (int j2 = 0; j2 < 4; j2++) {   // odd span: both terms in-reg
            int n = tp + 64 * j2;
            out[(k0 + 8 * r + 2 * g + 1) * HOP + n] = a[j2].y + a[j2 + 4].x;
        }
        if (r == 0 && g == 0) {   // tile front boundary
#pragma unroll
            for (int j2 = 0; j2 < 4; j2++)
                atomicAdd(&out[k0 * HOP + tp + 64 * j2], a[j2].x);
        }
        if (r == 1 && g == 3) {   // tile tail boundary
#pragma unroll
            for (int j2 = 0; j2 < 4; j2++) {
                int m = (k0 + CH) * HOP + tp + 64 * j2;
                if (m < PIANO) atomicAdd(&out[m], a[j2 + 4].y);
            }
        }
        __syncthreads();
        if (g >= 1) {   // even span within round
#pragma unroll
            for (int j2 = 0; j2 < 4; j2++) {
                int n = tp + 64 * j2;
                out[(k0 + 8 * r + 2 * g) * HOP + n] = a[j2].x + sh_hi[(g - 1) * 256 + n];
            }
        }
        if (r == 1 && g == 0) {   // cross-round even span (blk 8)
#pragma unroll
            for (int j2 = 0; j2 < 4; j2++) {
                int n = tp + 64 * j2;
                out[(k0 + 8) * HOP + n] = a[j2].x + sh_hi[3 * 256 + n];
            }
        }
    }
}

extern "C" void kernel_launch(void* const* d_in, const int* in_sizes, int n_in,
                              void* d_out, int out_size) {
    const float* env   = (const float*)d_in[1];
    const float* tf_r  = (const float*)d_in[2];
    const float* tf_i  = (const float*)d_in[3];
    const float* etf_r = (const float*)d_in[4];
    const float* etf_i = (const float*)d_in[5];
    const float* noise = (const float*)d_in[6];
    float* out = (float*)d_out;

    kA7<<<NSTEPS / 8, 256>>>(env, noise, etf_r, etf_i, out);
    kBC<<<NB_BC, 256>>>(tf_r, tf_i, out);
}

// round 17
// speedup vs baseline: 1.0538x; 1.0538x over previous
#include <cuda_runtime.h>
#include <math.h>

#define NSTEPS   10240
#define NBINS    257
#define BLK      512
#define HOP      256
#define PIANO    2621440
#define ENVLEN   327744
#define SQRTN_INV 0.04419417382415922f   // 1/sqrt(512)
#define TWO_PI   6.283185307179586f

// WARM=4: rel_err ladder (6.8e-7 @6, 1.9e-6 @5, x~2.8/step) -> ~6e-6, 150x margin.
#define CH   8
#define WARM 4
#define NB_BC (NSTEPS / CH)   // 1280 fused scan+iFFT blocks

// padded row stride (float2) for the 8x64 transpose buffer
#define RPAD 66

// +1 row padding: the final iteration's (unused) ispec prefetch may touch
// row NSTEPS, so the clamp in the hot loop can be dropped.
__device__ float2 g_ispec[(NSTEPS + 1) * NBINS];

__device__ __forceinline__ float2 cmulf(float2 a, float2 b) {
    return make_float2(a.x * b.x - a.y * b.y, a.x * b.y + a.y * b.x);
}
__device__ __forceinline__ float2 cadd(float2 a, float2 b) { return make_float2(a.x + b.x, a.y + b.y); }
__device__ __forceinline__ float2 csub(float2 a, float2 b) { return make_float2(a.x - b.x, a.y - b.y); }
__device__ __forceinline__ float2 cmuli(float2 a, float dir) { return make_float2(-dir * a.y, dir * a.x); }

__device__ __forceinline__ void dft8(float2 a[8], float dir) {
    const float r = 0.70710678118654752f;
    float2 e0 = cadd(a[0], a[4]), e1 = csub(a[0], a[4]);
    float2 o0 = cadd(a[2], a[6]), o1 = cmuli(csub(a[2], a[6]), dir);
    float2 E0 = cadd(e0, o0), E1 = cadd(e1, o1), E2 = csub(e0, o0), E3 = csub(e1, o1);
    float2 f0 = cadd(a[1], a[5]), f1 = csub(a[1], a[5]);
    float2 g0 = cadd(a[3], a[7]), g1 = cmuli(csub(a[3], a[7]), dir);
    float2 O0 = cadd(f0, g0), O1 = cadd(f1, g1), O2 = csub(f0, g0), O3 = csub(f1, g1);
    O1 = cmulf(O1, make_float2( r, dir * r));
    O2 = cmuli(O2, dir);
    O3 = cmulf(O3, make_float2(-r, dir * r));
    a[0] = cadd(E0, O0); a[1] = cadd(E1, O1); a[2] = cadd(E2, O2); a[3] = cadd(E3, O3);
    a[4] = csub(E0, O0); a[5] = csub(E1, O1); a[6] = csub(E2, O2); a[7] = csub(E3, O3);
}

__device__ __forceinline__ void twiddle8(float2 a[8], float ang) {
    float s1, c1, s4, c4;
    __sincosf(ang, &s1, &c1);
    __sincosf(4.0f * ang, &s4, &c4);
    float2 w1 = make_float2(c1, s1), w4 = make_float2(c4, s4);
    float2 w2 = cmulf(w1, w1), w3 = cmulf(w2, w1);
    a[1] = cmulf(a[1], w1);
    a[2] = cmulf(a[2], w2);
    a[3] = cmulf(a[3], w3);
    a[4] = cmulf(a[4], w4);
    a[5] = cmulf(a[5], cmulf(w4, w1));
    a[6] = cmulf(a[6], cmulf(w4, w2));
    a[7] = cmulf(a[7], cmulf(w4, w3));
}

// 3-stage radix-8 512-pt FFT. Input: a[n1] = x[64*n1 + t], t in [0,64).
// Output: a[j2] = X[tp + 64*j2], tp = (t&7) + 8*(t>>3).
__device__ __forceinline__ void fft512_r8(float2 a[8], float2* W, int t, float dir) {
    dft8(a, dir);
    twiddle8(a, dir * TWO_PI * (float)t * (1.0f / 512.0f));
#pragma unroll
    for (int k1 = 0; k1 < 8; k1++) W[k1 * RPAD + t] = a[k1];
    __syncthreads();
    int k1 = t >> 3, m2 = t & 7;
#pragma unroll
    for (int m1 = 0; m1 < 8; m1++) a[m1] = W[k1 * RPAD + 8 * m1 + m2];
    dft8(a, dir);
    twiddle8(a, dir * TWO_PI * (float)m2 * (1.0f / 64.0f));
#pragma unroll
    for (int j1 = 0; j1 < 8; j1++) W[k1 * RPAD + 8 * j1 + m2] = a[j1];  // per-thread in-place
    __syncthreads();
    int j1 = t >> 3, k1b = t & 7;
#pragma unroll
    for (int q = 0; q < 8; q++) a[q] = W[k1b * RPAD + 8 * j1 + q];
    dft8(a, dir);
}

// Kernel A: forward excitation spectra + zero-init of this tile's OA
// boundary span (consumed by kBC's atomics; kA grid maps 1:1 to spans).
__global__ void kA7(const float* __restrict__ env, const float* __restrict__ noise,
                    const float* __restrict__ etf_r, const float* __restrict__ etf_i,
                    float* __restrict__ out) {
    __shared__ float2 work[4][8 * RPAD];
    __shared__ float  exc [2304];
    __shared__ float  es  [290];
    int tid = threadIdx.x;
    int g = tid >> 6, t = tid & 63;
    const int base = blockIdx.x * 8;
    const int k0 = base + 2 * g;
    float2* W = work[g];

    out[blockIdx.x * 2048 + tid] = 0.0f;   // boundary span zero-init

    {
        int g0i = base * 32 - 1;
        int i0 = g0i + tid;
        float e0 = __ldg(&env[max(i0, 0)]);
        es[tid] = e0 * e0;
        if (tid < 34) {
            float e1 = __ldg(&env[min(g0i + 256 + tid, ENVLEN - 1)]);
            es[256 + tid] = e1 * e1;
        }
    }
    __syncthreads();

#pragma unroll
    for (int u = 0; u < 9; u++) {
        int o = tid + 256 * u;
        int m = o >> 3, j = o & 7;
        int s_lo = m + (j >> 2);
        float w = 0.0625f + 0.125f * (float)((j + 4) & 7);
        float lo = es[s_lo], hi = es[s_lo + 1];
        exc[o] = lo + (hi - lo) * w;
    }
    __syncthreads();

    float2 a[8];
#pragma unroll
    for (int n1 = 0; n1 < 8; n1++) {
        int n = 64 * n1 + t;
        float v0 = noise[k0 * BLK + n]       * exc[2 * g * HOP + n];
        float v1 = noise[(k0 + 1) * BLK + n] * exc[(2 * g + 1) * HOP + n];
        a[n1] = make_float2(v0, v1);
    }
    fft512_r8(a, W, t, -1.0f);
    __syncthreads();

    int tp = (t & 7) + 8 * (t >> 3);
#pragma unroll
    for (int j2 = 0; j2 < 8; j2++) W[tp + 64 * j2] = a[j2];
    __syncthreads();

    for (int j = t; j < NBINS; j += 64) {
        float2 Z  = W[j];
        float2 Zc = W[(512 - j) & 511];
        Zc.y = -Zc.y;
        float2 X0 = make_float2(0.5f * (Z.x + Zc.x), 0.5f * (Z.y + Zc.y));
        float2 D  = make_float2(Z.x - Zc.x, Z.y - Zc.y);
        float2 X1 = make_float2(0.5f * D.y, -0.5f * D.x);
        X0.x *= SQRTN_INV; X0.y *= SQRTN_INV;
        X1.x *= SQRTN_INV; X1.y *= SQRTN_INV;
        float2 e = make_float2(etf_r[j], etf_i[j]);
        float2 I0 = cmulf(X0, e);
        float2 I1 = cmulf(X1, e);
        if (j == 0 || j == 256) { I0.y = 0.0f; I1.y = 0.0f; }
        g_ispec[k0 * NBINS + j]       = I0;
        g_ispec[(k0 + 1) * NBINS + j] = I1;
    }
}

// ---------------------------------------------------------------------------
// Kernel BC (fused scan + inverse FFT + overlap-add), 256 threads, PDL.
// tf prefetch (independent of kA) issues BEFORE cudaGridDependencySynchronize;
// all g_ispec / out accesses sit after it.
// ---------------------------------------------------------------------------
__global__ void __launch_bounds__(256, 6)
kBC(const float* __restrict__ tf_r, const float* __restrict__ tf_i,
    float* __restrict__ out) {
    __shared__ float2 workspec[4][526];        // FFT work (union: spec 8x257)
    __shared__ float  uni[2 * 259 * 2];        // shY (phase 1) / sh_hi (phase 3)
    float2* specF = &workspec[0][0];
    float2* shY   = (float2*)uni;
    float*  sh_hi = uni;

    const int tid = threadIdx.x;
    const bool dual = (tid == 255);
    const int b = blockIdx.x;
    const int k0 = b * CH;

    // ---- Phase 1: scan ----
    int k_start = k0 - WARM;
    if (k_start < 0) k_start = 0;
    const int k_last = k0 + CH - 2;

    // independent of kA: issue before the PDL dependency wait
    float2 tfv = make_float2(__ldg(&tf_r[k_start * NBINS + tid]),
                             __ldg(&tf_i[k_start * NBINS + tid]));
    float tf2 = 0.f;
    if (dual) tf2 = __ldg(&tf_r[k_start * NBINS + 256]);

    cudaGridDependencySynchronize();   // wait for kA's g_ispec + out zero-init

    float2 S  = g_ispec[k_start * NBINS + tid];
    float2 iv = g_ispec[(k_start + 1) * NBINS + tid];
    float S2 = 0.f, iv2 = 0.f;
    if (dual) {
        S2  = g_ispec[k_start * NBINS + 256].x;
        iv2 = g_ispec[(k_start + 1) * NBINS + 256].x;
    }
    if (k_start == k0) {
        specF[tid] = S;
        if (dual) specF[256] = make_float2(S2, 0.f);
    }

    int p = 0;
#pragma unroll 2
    for (int kk = k_start; kk <= k_last; kk++, p ^= 1) {
        float2* buf = shY + p * 259;
        float2 Y = cmulf(tfv, S);
        if (tid == 0) Y.y = 0.0f;
        buf[tid + 1] = Y;
        if (tid == 1) buf[0] = make_float2(Y.x, -Y.y);
        float Y2 = 0.f;
        if (dual) {
            Y2 = tf2 * S2;                      // bin 256: real scalar
            buf[257] = make_float2(Y2, 0.0f);
        }
        int kn = kk + 1;
        float2 tfn = make_float2(__ldg(&tf_r[kn * NBINS + tid]),
                                 __ldg(&tf_i[kn * NBINS + tid]));
        float2 ivn = g_ispec[(kk + 2) * NBINS + tid];   // padded: no clamp
        float tfn2 = 0.f, ivn2 = 0.f;
        if (dual) {
            tfn2 = __ldg(&tf_r[kn * NBINS + 256]);
            ivn2 = g_ispec[(kk + 2) * NBINS + 256].x;
        }
        __syncthreads();
        float2 Ym = buf[tid];
        float2 Yp = buf[tid + 2];
        S.x = 0.54f * Y.x - 0.23f * (Ym.x + Yp.x) + iv.x;   // Y0 = own reg
        S.y = 0.54f * Y.y - 0.23f * (Ym.y + Yp.y) + iv.y;
        bool st = (kk + 1 >= k0);
        if (st) specF[(kk + 1 - k0) * NBINS + tid] = S;
        if (dual) {
            S2 = 0.54f * Y2 - 0.46f * Y.x + iv2;
            if (st) specF[(kk + 1 - k0) * NBINS + 256] = make_float2(S2, 0.f);
        }
        tfv = tfn; iv = ivn; tf2 = tfn2; iv2 = ivn2;
    }
    __syncthreads();    // spec complete; shY dead

    // ---- Phase 2: 4 paired inverse FFTs ----
    const int g = tid >> 6, t = tid & 63;
    float2 a[8];
    {
        const float2* s0 = specF + (2 * g) * NBINS;
        const float2* s1 = specF + (2 * g + 1) * NBINS;
#pragma unroll
        for (int n1 = 0; n1 < 8; n1++) {
            int n = 64 * n1 + t;
            if (n <= 256) {
                float2 S0 = s0[n], S1 = s1[n];
                a[n1] = make_float2(S0.x - S1.y, S0.y + S1.x);
            } else {
                int j = 512 - n;
                float2 S0 = s0[j], S1 = s1[j];
                a[n1] = make_float2(S0.x + S1.y, S1.x - S0.y);
            }
        }
    }
    __syncthreads();    // all spec reads done -> FFT may overwrite workspec
    fft512_r8(a, &workspec[g][0], t, +1.0f);

    // ---- Phase 3: register-direct overlap-add ----
#pragma unroll
    for (int q = 0; q < 8; q++) { a[q].x *= SQRTN_INV; a[q].y *= SQRTN_INV; }
    const int tp = (t & 7) + 8 * (t >> 3);

    if (g < 3) {
#pragma unroll
        for (int j2 = 0; j2 < 4; j2++) sh_hi[g * 256 + tp + 64 * j2] = a[j2 + 4].y;
    }
#pragma unroll
    for (int j2 = 0; j2 < 4; j2++) {
        int n = tp + 64 * j2;
        out[(k0 + 2 * g + 1) * HOP + n] = a[j2].y + a[j2 + 4].x;
    }
    if (g == 0) {
#pragma unroll
        for (int j2 = 0; j2 < 4; j2++)
            atomicAdd(&out[k0 * HOP + tp + 64 * j2], a[j2].x);
    }
    if (g == 3) {
#pragma unroll
        for (int j2 = 0; j2 < 4; j2++) {
            int m = (k0 + 8) * HOP + tp + 64 * j2;
            if (m < PIANO) atomicAdd(&out[m], a[j2 + 4].y);
        }
    }
    __syncthreads();
    if (g >= 1) {
#pragma unroll
        for (int j2 = 0; j2 < 4; j2++) {
            int n = tp + 64 * j2;
            out[(k0 + 2 * g) * HOP + n] = a[j2].x + sh_hi[(g - 1) * 256 + n];
        }
    }
}

extern "C" void kernel_launch(void* const* d_in, const int* in_sizes, int n_in,
                              void* d_out, int out_size) {
    const float* env   = (const float*)d_in[1];
    const float* tf_r  = (const float*)d_in[2];
    const float* tf_i  = (const float*)d_in[3];
    const float* etf_r = (const float*)d_in[4];
    const float* etf_i = (const float*)d_in[5];
    const float* noise = (const float*)d_in[6];
    float* out = (float*)d_out;

    kA7<<<NSTEPS / 8, 256>>>(env, noise, etf_r, etf_i, out);

    // PDL: kBC's prologue (launch + tf prefetch) overlaps kA's tail; the
    // device-side cudaGridDependencySynchronize enforces the data dependency.
    cudaLaunchConfig_t cfg = {};
    cfg.gridDim  = dim3(NB_BC);
    cfg.blockDim = dim3(256);
    cfg.dynamicSmemBytes = 0;
    cfg.stream = 0;
    cudaLaunchAttribute attrs[1];
    attrs[0].id = cudaLaunchAttributeProgrammaticStreamSerialization;
    attrs[0].val.programmaticStreamSerializationAllowed = 1;
    cfg.attrs = attrs;
    cfg.numAttrs = 1;
    cudaLaunchKernelEx(&cfg, kBC, tf_r, tf_i, out);
}